// round 5
// baseline (speedup 1.0000x reference)
#include <cuda_runtime.h>
#include <cuda_fp16.h>
#include <cstdint>
#include <math.h>

#define EPS    1e-6f
#define MARGIN 0.3f
#define DDIM   128
#define MAXB   16384
#define JSPLIT 8
#define TM     128      // anchor rows per CTA
#define TNT    128      // negatives per tile
#define PADH   136      // halfs per smem row (272 B) -> conflict-free ldmatrix
#define ROWB   272      // bytes per smem row
#define NBUF_B 34816    // bytes per N buffer (128*272)

// ---------------- scratch (no allocations allowed) ----------------
__device__ __align__(16) __half g_Ah[MAXB * DDIM];
__device__ __align__(16) __half g_Nh[MAXB * DDIM];
__device__ __align__(16) float  g_beta[MAXB];
__device__ float g_posd[MAXB];
__device__ float g_pval[JSPLIT][MAXB];
__device__ int   g_pidx[JSPLIT][MAXB];
__device__ float g_rowloss[MAXB];

// ---------------- smem layout (bytes) ----------------
#define OFF_RED_V  0                 // float[128][4]
#define OFF_RED_I  2048              // int[128][4]
#define OFF_BS     4096              // float[4][128] beta ring
#define OFF_A      6144              // __half[128][PADH]
#define OFF_N      40960             // 3 x N buffer
#define SMEM_TOTAL 145408

__device__ __forceinline__ void mma_f16(float c[4], const uint32_t a[4],
                                        uint32_t b0, uint32_t b1) {
    asm volatile(
        "mma.sync.aligned.m16n8k16.row.col.f32.f16.f16.f32 "
        "{%0,%1,%2,%3}, {%4,%5,%6,%7}, {%8,%9}, {%0,%1,%2,%3};\n"
        : "+f"(c[0]), "+f"(c[1]), "+f"(c[2]), "+f"(c[3])
        : "r"(a[0]), "r"(a[1]), "r"(a[2]), "r"(a[3]), "r"(b0), "r"(b1));
}

__device__ __forceinline__ void ldsm_x4(uint32_t r[4], uint32_t addr) {
    asm volatile("ldmatrix.sync.aligned.m8n8.x4.shared.b16 {%0,%1,%2,%3}, [%4];"
                 : "=r"(r[0]), "=r"(r[1]), "=r"(r[2]), "=r"(r[3]) : "r"(addr));
}

__device__ __forceinline__ void cp_async16(void* dst_smem, const void* src_gmem) {
    unsigned d = (unsigned)__cvta_generic_to_shared(dst_smem);
    asm volatile("cp.async.cg.shared.global [%0], [%1], 16;\n" :: "r"(d), "l"(src_gmem));
}
__device__ __forceinline__ void cp_commit() { asm volatile("cp.async.commit_group;\n"); }

// ---------------- kernel 1: per-row stats + fp16 conversion ----------------
__global__ void prep_kernel(const float* __restrict__ anc, const float* __restrict__ pos,
                            const float* __restrict__ neg, int B) {
    int warp = (blockIdx.x * blockDim.x + threadIdx.x) >> 5;
    int lane = threadIdx.x & 31;
    if (warp >= B) return;
    const float4 a = ((const float4*)(anc + (size_t)warp * DDIM))[lane];
    const float4 p = ((const float4*)(pos + (size_t)warp * DDIM))[lane];
    const float4 n = ((const float4*)(neg + (size_t)warp * DDIM))[lane];

    __half2* ah = (__half2*)(g_Ah + (size_t)warp * DDIM);
    __half2* nh = (__half2*)(g_Nh + (size_t)warp * DDIM);
    ah[lane * 2]     = __floats2half2_rn(a.x, a.y);
    ah[lane * 2 + 1] = __floats2half2_rn(a.z, a.w);
    nh[lane * 2]     = __floats2half2_rn(n.x, n.y);
    nh[lane * 2 + 1] = __floats2half2_rn(n.z, n.w);

    float d0 = a.x - p.x + EPS, d1 = a.y - p.y + EPS, d2 = a.z - p.z + EPS, d3 = a.w - p.w + EPS;
    float pd = d0*d0 + d1*d1 + d2*d2 + d3*d3;
    float nn = n.x*n.x + n.y*n.y + n.z*n.z + n.w*n.w;
    float ns = n.x + n.y + n.z + n.w;
    #pragma unroll
    for (int off = 16; off; off >>= 1) {
        pd += __shfl_xor_sync(0xffffffffu, pd, off);
        nn += __shfl_xor_sync(0xffffffffu, nn, off);
        ns += __shfl_xor_sync(0xffffffffu, ns, off);
    }
    if (lane == 0) {
        g_posd[warp] = sqrtf(pd);
        g_beta[warp] = nn - 2.0f * EPS * ns;
    }
}

// ---------------- kernel 2: fp16 GEMM + fused per-row argmin ----------------
// 256 threads, 1 CTA/SM. Warp grid 2(M) x 4(N); warp tile 64x32.
__global__ void __launch_bounds__(256, 1) gemm_argmin_kernel(int B) {
    extern __shared__ char smem[];
    float* Bs = (float*)(smem + OFF_BS);
    float* Rv = (float*)(smem + OFF_RED_V);
    int*   Ri = (int*)(smem + OFF_RED_I);

    const int tid = threadIdx.x, lane = tid & 31, wid = tid >> 5;
    const int warpM = wid >> 2;                    // 0..1 -> 64 rows
    const int warpN = wid & 3;                     // 0..3 -> 32 cols
    const int g = lane >> 2, q = lane & 3;

    const int jlen   = B / JSPLIT;                 // 2048
    const int rowT   = blockIdx.x / JSPLIT;
    const int js     = blockIdx.x % JSPLIT;
    const int row0   = rowT * TM;
    const int jbase0 = js * jlen;
    const int ntiles = jlen / TNT;                 // 16

    unsigned sb = (unsigned)__cvta_generic_to_shared(smem);

    // ldmatrix lane base addresses
    // A: lanes 0-15 -> m rows 0-15, lanes 16-31 -> same rows, +16B (k8)
    const uint32_t aBase = sb + OFF_A
        + (uint32_t)(warpM * 64 + (lane & 15)) * ROWB + (uint32_t)(lane >> 4) * 16;
    // B: lanes {0-7,8-15,16-23,24-31} -> {n0-7 k0, n0-7 k8, n8-15 k0, n8-15 k8}
    const uint32_t bRel = (uint32_t)(warpN * 32 + (lane & 7) + ((lane >> 4) & 1) * 8) * ROWB
        + (uint32_t)((lane >> 3) & 1) * 16;

    auto load_A = [&]() {
        for (int i = tid; i < TM * 16; i += 256) {
            int r = i >> 4, f = i & 15;
            cp_async16(smem + OFF_A + r * ROWB + f * 16,
                       g_Ah + (size_t)(row0 + r) * DDIM + f * 8);
        }
    };
    auto load_N = [&](int tile) {
        if (tile < ntiles) {
            const int jb = jbase0 + tile * TNT;
            char* dst = smem + OFF_N + (tile % 3) * NBUF_B;
            for (int i = tid; i < TNT * 16; i += 256) {
                int r = i >> 4, f = i & 15;
                cp_async16(dst + r * ROWB + f * 16, g_Nh + (size_t)(jb + r) * DDIM + f * 8);
            }
            if (tid < 32)
                cp_async16(Bs + (tile & 3) * 128 + tid * 4, g_beta + jb + tid * 4);
        }
    };

    load_A(); load_N(0); cp_commit();
    load_N(1); cp_commit();

    const float INFF = __int_as_float(0x7f800000);
    float best[8];
    int   bidx[8];
    #pragma unroll
    for (int s = 0; s < 8; ++s) { best[s] = INFF; bidx[s] = 0; }

    for (int t = 0; t < ntiles; ++t) {
        asm volatile("cp.async.wait_group 1;\n");
        __syncthreads();

        float acc[4][4][4];
        #pragma unroll
        for (int rt = 0; rt < 4; ++rt)
            #pragma unroll
            for (int nt = 0; nt < 4; ++nt)
                #pragma unroll
                for (int c = 0; c < 4; ++c) acc[rt][nt][c] = 0.0f;

        const uint32_t bBase = sb + OFF_N + (uint32_t)(t % 3) * NBUF_B + bRel;

        #pragma unroll
        for (int kk = 0; kk < 8; ++kk) {
            const uint32_t kOff = (uint32_t)kk * 32;
            uint32_t af[4][4], bf[2][4];
            #pragma unroll
            for (int rt = 0; rt < 4; ++rt)
                ldsm_x4(af[rt], aBase + (uint32_t)rt * (16 * ROWB) + kOff);
            #pragma unroll
            for (int np = 0; np < 2; ++np)
                ldsm_x4(bf[np], bBase + (uint32_t)np * (16 * ROWB) + kOff);
            #pragma unroll
            for (int rt = 0; rt < 4; ++rt)
                #pragma unroll
                for (int nt = 0; nt < 4; ++nt)
                    mma_f16(acc[rt][nt], af[rt], bf[nt >> 1][(nt & 1) * 2],
                            bf[nt >> 1][(nt & 1) * 2 + 1]);
        }

        // start prefetch of t+2 before the epilogue (buffer (t+2)%3 = (t-1)%3,
        // everyone is past its MMA reads thanks to the barrier above)
        load_N(t + 2);
        cp_commit();

        // epilogue: fold beta, running argmin (overlaps in-flight cp.async)
        const float* bsp = Bs + (t & 3) * 128;
        const int jb = jbase0 + t * TNT;
        #pragma unroll
        for (int rt = 0; rt < 4; ++rt) {
            const int s0 = rt * 2, s1 = rt * 2 + 1;
            #pragma unroll
            for (int nt = 0; nt < 4; ++nt) {
                int jc = warpN * 32 + nt * 8 + 2 * q;
                float b0 = bsp[jc], b1 = bsp[jc + 1];
                float v00 = fmaf(-2.0f, acc[rt][nt][0], b0);
                float v01 = fmaf(-2.0f, acc[rt][nt][1], b1);
                float v10 = fmaf(-2.0f, acc[rt][nt][2], b0);
                float v11 = fmaf(-2.0f, acc[rt][nt][3], b1);
                if (v00 < best[s0]) { best[s0] = v00; bidx[s0] = jb + jc; }
                if (v01 < best[s0]) { best[s0] = v01; bidx[s0] = jb + jc + 1; }
                if (v10 < best[s1]) { best[s1] = v10; bidx[s1] = jb + jc; }
                if (v11 < best[s1]) { best[s1] = v11; bidx[s1] = jb + jc + 1; }
            }
        }
    }

    // quad reduce (lanes sharing a row differ only in q), tie -> smaller index
    #pragma unroll
    for (int s = 0; s < 8; ++s) {
        float v = best[s]; int ix = bidx[s];
        #pragma unroll
        for (int off = 1; off <= 2; off <<= 1) {
            float ov = __shfl_xor_sync(0xffffffffu, v, off);
            int   oi = __shfl_xor_sync(0xffffffffu, ix, off);
            if (ov < v || (ov == v && oi < ix)) { v = ov; ix = oi; }
        }
        best[s] = v; bidx[s] = ix;
    }
    if (q == 0) {
        #pragma unroll
        for (int s = 0; s < 8; ++s) {
            int r = warpM * 64 + (s >> 1) * 16 + (s & 1) * 8 + g;
            Rv[r * 4 + warpN] = best[s];
            Ri[r * 4 + warpN] = bidx[s];
        }
    }
    __syncthreads();
    if (tid < TM) {
        float v = Rv[tid * 4]; int ix = Ri[tid * 4];
        #pragma unroll
        for (int w = 1; w < 4; ++w) {
            float ov = Rv[tid * 4 + w]; int oi = Ri[tid * 4 + w];
            if (ov < v || (ov == v && oi < ix)) { v = ov; ix = oi; }
        }
        g_pval[js][row0 + tid] = v;
        g_pidx[js][row0 + tid] = ix;
    }
}

// ---------------- kernel 3: combine partials, exact fp32 neg_dist, row loss ----------------
__global__ void combine_kernel(const float* __restrict__ anc, const float* __restrict__ neg, int B) {
    int warp = (blockIdx.x * blockDim.x + threadIdx.x) >> 5;
    int lane = threadIdx.x & 31;
    if (warp >= B) return;
    const float INFF = __int_as_float(0x7f800000);
    float v = INFF; int ix = 0x7fffffff;
    if (lane < JSPLIT) { v = g_pval[lane][warp]; ix = g_pidx[lane][warp]; }
    #pragma unroll
    for (int off = 16; off; off >>= 1) {
        float ov = __shfl_xor_sync(0xffffffffu, v, off);
        int   oi = __shfl_xor_sync(0xffffffffu, ix, off);
        if (ov < v || (ov == v && oi < ix)) { v = ov; ix = oi; }
    }
    const float4 a = ((const float4*)(anc + (size_t)warp * DDIM))[lane];
    const float4 n = ((const float4*)(neg + (size_t)ix * DDIM))[lane];
    float d0 = a.x - n.x + EPS, d1 = a.y - n.y + EPS, d2 = a.z - n.z + EPS, d3 = a.w - n.w + EPS;
    float nd = d0*d0 + d1*d1 + d2*d2 + d3*d3;
    #pragma unroll
    for (int off = 16; off; off >>= 1) nd += __shfl_xor_sync(0xffffffffu, nd, off);
    if (lane == 0) {
        float t = g_posd[warp] - sqrtf(nd) + MARGIN;
        g_rowloss[warp] = t > 0.0f ? t : 0.0f;
    }
}

// ---------------- kernel 4: deterministic mean ----------------
__global__ void final_kernel(float* __restrict__ out, int B) {
    __shared__ float sm[1024];
    float s = 0.0f;
    const float4* rl = (const float4*)g_rowloss;
    for (int i = threadIdx.x; i < B / 4; i += 1024) {
        float4 v = rl[i];
        s += (v.x + v.y) + (v.z + v.w);
    }
    sm[threadIdx.x] = s;
    __syncthreads();
    for (int w = 512; w; w >>= 1) {
        if (threadIdx.x < w) sm[threadIdx.x] += sm[threadIdx.x + w];
        __syncthreads();
    }
    if (threadIdx.x == 0) out[0] = sm[0] / (float)B;
}

// ---------------- launch ----------------
extern "C" void kernel_launch(void* const* d_in, const int* in_sizes, int n_in,
                              void* d_out, int out_size) {
    const float* anc = (const float*)d_in[0];
    const float* pos = (const float*)d_in[1];
    const float* neg = (const float*)d_in[2];
    int B = in_sizes[0] / DDIM;
    float* out = (float*)d_out;

    cudaFuncSetAttribute(gemm_argmin_kernel, cudaFuncAttributeMaxDynamicSharedMemorySize, SMEM_TOTAL);

    prep_kernel<<<(B + 7) / 8, 256>>>(anc, pos, neg, B);
    gemm_argmin_kernel<<<(B / TM) * JSPLIT, 256, SMEM_TOTAL>>>(B);
    combine_kernel<<<(B + 7) / 8, 256>>>(anc, neg, B);
    final_kernel<<<1, 1024>>>(out, B);
}

// round 7
// speedup vs baseline: 1.2397x; 1.2397x over previous
#include <cuda_runtime.h>
#include <cuda_fp16.h>
#include <cstdint>
#include <math.h>

#define EPS    1e-6f
#define MARGIN 0.3f
#define DDIM   128
#define MAXB   16384
#define JSPLIT 8
#define TM     128      // anchor rows per CTA
#define TNT    128      // negatives per tile
#define ROWB   144      // bytes per smem row: 128B data + 16B pad -> conflict-free ldmatrix
#define NBUF_B 18432    // bytes per tile buffer (128*144)

// ---------------- scratch (no allocations allowed) ----------------
__device__ __align__(16) signed char g_Ai8[MAXB * DDIM];
__device__ __align__(16) signed char g_Ni8[MAXB * DDIM];
__device__ __align__(16) float g_ascale[MAXB];
__device__ __align__(16) float g_nscale[MAXB];
__device__ __align__(16) float g_beta[MAXB];    // exact ||n||^2 - 2*eps*sum(n)
__device__ float g_posd[MAXB];
__device__ int   g_pidx[JSPLIT][MAXB];          // slot-winner candidates per row
__device__ float g_rowloss[MAXB];

// ---------------- smem layout (bytes) ----------------
#define OFF_RED_V  0                 // float[128][4]
#define OFF_RED_I  2048              // int[128][4]
#define OFF_BS     4096              // float[4][128] beta ring
#define OFF_TS     6144              // float[4][128] nscale ring
#define OFF_A      8192              // 128 x ROWB int8 tile (18432 B)
#define OFF_N      26624             // 3 x tile buffer (55296 B)
#define SMEM_TOTAL 81920

__device__ __forceinline__ void mma_s8(int c[4], const uint32_t a[4],
                                       uint32_t b0, uint32_t b1) {
    asm volatile(
        "mma.sync.aligned.m16n8k32.row.col.s32.s8.s8.s32 "
        "{%0,%1,%2,%3}, {%4,%5,%6,%7}, {%8,%9}, {%0,%1,%2,%3};\n"
        : "+r"(c[0]), "+r"(c[1]), "+r"(c[2]), "+r"(c[3])
        : "r"(a[0]), "r"(a[1]), "r"(a[2]), "r"(a[3]), "r"(b0), "r"(b1));
}

__device__ __forceinline__ void ldsm_x4(uint32_t r[4], uint32_t addr) {
    asm volatile("ldmatrix.sync.aligned.m8n8.x4.shared.b16 {%0,%1,%2,%3}, [%4];"
                 : "=r"(r[0]), "=r"(r[1]), "=r"(r[2]), "=r"(r[3]) : "r"(addr));
}

__device__ __forceinline__ void cp_async16(void* dst_smem, const void* src_gmem) {
    unsigned d = (unsigned)__cvta_generic_to_shared(dst_smem);
    asm volatile("cp.async.cg.shared.global [%0], [%1], 16;\n" :: "r"(d), "l"(src_gmem));
}
__device__ __forceinline__ void cp_commit() { asm volatile("cp.async.commit_group;\n"); }

// ---------------- kernel 1: stats + per-row int8 quantization ----------------
__global__ void prep_kernel(const float* __restrict__ anc, const float* __restrict__ pos,
                            const float* __restrict__ neg, int B) {
    int warp = (blockIdx.x * blockDim.x + threadIdx.x) >> 5;
    int lane = threadIdx.x & 31;
    if (warp >= B) return;
    const float4 a = ((const float4*)(anc + (size_t)warp * DDIM))[lane];
    const float4 p = ((const float4*)(pos + (size_t)warp * DDIM))[lane];
    const float4 n = ((const float4*)(neg + (size_t)warp * DDIM))[lane];

    float amax = fmaxf(fmaxf(fabsf(a.x), fabsf(a.y)), fmaxf(fabsf(a.z), fabsf(a.w)));
    float nmax = fmaxf(fmaxf(fabsf(n.x), fabsf(n.y)), fmaxf(fabsf(n.z), fabsf(n.w)));
    float d0 = a.x - p.x + EPS, d1 = a.y - p.y + EPS, d2 = a.z - p.z + EPS, d3 = a.w - p.w + EPS;
    float pd = d0*d0 + d1*d1 + d2*d2 + d3*d3;
    float nn = n.x*n.x + n.y*n.y + n.z*n.z + n.w*n.w;
    float ns = n.x + n.y + n.z + n.w;
    #pragma unroll
    for (int off = 16; off; off >>= 1) {
        amax = fmaxf(amax, __shfl_xor_sync(0xffffffffu, amax, off));
        nmax = fmaxf(nmax, __shfl_xor_sync(0xffffffffu, nmax, off));
        pd += __shfl_xor_sync(0xffffffffu, pd, off);
        nn += __shfl_xor_sync(0xffffffffu, nn, off);
        ns += __shfl_xor_sync(0xffffffffu, ns, off);
    }
    amax = fmaxf(amax, 1e-30f);
    nmax = fmaxf(nmax, 1e-30f);
    float ia = 127.0f / amax, in_ = 127.0f / nmax;

    char4 qa = make_char4((char)__float2int_rn(a.x * ia), (char)__float2int_rn(a.y * ia),
                          (char)__float2int_rn(a.z * ia), (char)__float2int_rn(a.w * ia));
    char4 qn = make_char4((char)__float2int_rn(n.x * in_), (char)__float2int_rn(n.y * in_),
                          (char)__float2int_rn(n.z * in_), (char)__float2int_rn(n.w * in_));
    ((char4*)(g_Ai8 + (size_t)warp * DDIM))[lane] = qa;
    ((char4*)(g_Ni8 + (size_t)warp * DDIM))[lane] = qn;

    if (lane == 0) {
        g_ascale[warp] = amax / 127.0f;
        g_nscale[warp] = nmax / 127.0f;
        g_posd[warp] = sqrtf(pd);
        g_beta[warp] = nn - 2.0f * EPS * ns;
    }
}

// ---------------- kernel 2: int8 GEMM + fused per-row argmin ----------------
// 256 threads, 1 CTA/SM. Warp grid 2(M) x 4(N); warp tile 64x32. K=128 in 4 k32 steps.
__global__ void __launch_bounds__(256, 1) gemm_argmin_kernel(int B) {
    extern __shared__ char smem[];
    float* Bs = (float*)(smem + OFF_BS);
    float* Ts = (float*)(smem + OFF_TS);
    float* Rv = (float*)(smem + OFF_RED_V);
    int*   Ri = (int*)(smem + OFF_RED_I);

    const int tid = threadIdx.x, lane = tid & 31, wid = tid >> 5;
    const int warpM = wid >> 2;                    // 0..1 -> 64 rows
    const int warpN = wid & 3;                     // 0..3 -> 32 cols
    const int g = lane >> 2, q = lane & 3;

    const int jlen   = B / JSPLIT;                 // 2048
    const int rowT   = blockIdx.x / JSPLIT;
    const int js     = blockIdx.x % JSPLIT;
    const int row0   = rowT * TM;
    const int jbase0 = js * jlen;
    const int ntiles = jlen / TNT;                 // 16

    unsigned sb = (unsigned)__cvta_generic_to_shared(smem);

    // per-thread row scale factors: k = -2 * s_row (rows g and g+8 per 16-row slab)
    float kA[8];
    #pragma unroll
    for (int rt = 0; rt < 4; ++rt) {
        int r = row0 + warpM * 64 + rt * 16 + g;
        kA[rt * 2]     = -2.0f * g_ascale[r];
        kA[rt * 2 + 1] = -2.0f * g_ascale[r + 8];
    }

    // ldmatrix lane base addresses (row stride 144B -> 8-row phases tile all 32 banks)
    const uint32_t aBase = sb + OFF_A
        + (uint32_t)(warpM * 64 + (lane & 15)) * ROWB + (uint32_t)(lane >> 4) * 16;
    const uint32_t bRel = (uint32_t)(warpN * 32 + (lane & 7) + ((lane >> 4) & 1) * 8) * ROWB
        + (uint32_t)((lane >> 3) & 1) * 16;

    auto load_A = [&]() {
        for (int i = tid; i < TM * 8; i += 256) {      // 128 rows x 8 chunks of 16B
            int r = i >> 3, f = i & 7;
            cp_async16(smem + OFF_A + r * ROWB + f * 16,
                       g_Ai8 + (size_t)(row0 + r) * DDIM + f * 16);
        }
    };
    auto load_N = [&](int tile) {
        if (tile < ntiles) {
            const int jb = jbase0 + tile * TNT;
            char* dst = smem + OFF_N + (tile % 3) * NBUF_B;
            for (int i = tid; i < TNT * 8; i += 256) {
                int r = i >> 3, f = i & 7;
                cp_async16(dst + r * ROWB + f * 16, g_Ni8 + (size_t)(jb + r) * DDIM + f * 16);
            }
            if (tid < 32)
                cp_async16(Bs + (tile & 3) * 128 + tid * 4, g_beta + jb + tid * 4);
            else if (tid < 64)
                cp_async16(Ts + (tile & 3) * 128 + (tid - 32) * 4, g_nscale + jb + (tid - 32) * 4);
        }
    };

    load_A(); load_N(0); cp_commit();
    load_N(1); cp_commit();

    const float INFF = __int_as_float(0x7f800000);
    float best[8];
    int   bidx[8];
    #pragma unroll
    for (int s = 0; s < 8; ++s) { best[s] = INFF; bidx[s] = 0; }

    for (int t = 0; t < ntiles; ++t) {
        asm volatile("cp.async.wait_group 1;\n");
        __syncthreads();

        int acc[4][4][4];
        #pragma unroll
        for (int rt = 0; rt < 4; ++rt)
            #pragma unroll
            for (int nt = 0; nt < 4; ++nt)
                #pragma unroll
                for (int c = 0; c < 4; ++c) acc[rt][nt][c] = 0;

        const uint32_t bBase = sb + OFF_N + (uint32_t)(t % 3) * NBUF_B + bRel;

        #pragma unroll
        for (int kk = 0; kk < 4; ++kk) {
            const uint32_t kOff = (uint32_t)kk * 32;
            uint32_t af[4][4], bf[2][4];
            #pragma unroll
            for (int rt = 0; rt < 4; ++rt)
                ldsm_x4(af[rt], aBase + (uint32_t)rt * (16 * ROWB) + kOff);
            #pragma unroll
            for (int np = 0; np < 2; ++np)
                ldsm_x4(bf[np], bBase + (uint32_t)np * (16 * ROWB) + kOff);
            #pragma unroll
            for (int rt = 0; rt < 4; ++rt)
                #pragma unroll
                for (int nt = 0; nt < 4; ++nt)
                    mma_s8(acc[rt][nt], af[rt], bf[nt >> 1][(nt & 1) * 2],
                           bf[nt >> 1][(nt & 1) * 2 + 1]);
        }

        load_N(t + 2);
        cp_commit();

        // epilogue: v = beta_j - 2*s_i*t_j*c  (residual noise rescued exactly in combine)
        const float* bsp = Bs + (t & 3) * 128;
        const float* tsp = Ts + (t & 3) * 128;
        const int jb = jbase0 + t * TNT;
        #pragma unroll
        for (int nt = 0; nt < 4; ++nt) {
            const int jc = warpN * 32 + nt * 8 + 2 * q;
            const float b0 = bsp[jc], b1 = bsp[jc + 1];
            const float t0 = tsp[jc], t1 = tsp[jc + 1];
            #pragma unroll
            for (int rt = 0; rt < 4; ++rt) {
                const int s0 = rt * 2, s1 = rt * 2 + 1;
                const float kl = kA[rt * 2], kh = kA[rt * 2 + 1];
                float v00 = fmaf((float)acc[rt][nt][0], kl * t0, b0);
                float v01 = fmaf((float)acc[rt][nt][1], kl * t1, b1);
                float v10 = fmaf((float)acc[rt][nt][2], kh * t0, b0);
                float v11 = fmaf((float)acc[rt][nt][3], kh * t1, b1);
                if (v00 < best[s0]) { best[s0] = v00; bidx[s0] = jb + jc; }
                if (v01 < best[s0]) { best[s0] = v01; bidx[s0] = jb + jc + 1; }
                if (v10 < best[s1]) { best[s1] = v10; bidx[s1] = jb + jc; }
                if (v11 < best[s1]) { best[s1] = v11; bidx[s1] = jb + jc + 1; }
            }
        }
    }

    // quad reduce (lanes sharing a row differ only in q), tie -> smaller index
    #pragma unroll
    for (int s = 0; s < 8; ++s) {
        float v = best[s]; int ix = bidx[s];
        #pragma unroll
        for (int off = 1; off <= 2; off <<= 1) {
            float ov = __shfl_xor_sync(0xffffffffu, v, off);
            int   oi = __shfl_xor_sync(0xffffffffu, ix, off);
            if (ov < v || (ov == v && oi < ix)) { v = ov; ix = oi; }
        }
        best[s] = v; bidx[s] = ix;
    }
    if (q == 0) {
        #pragma unroll
        for (int s = 0; s < 8; ++s) {
            int r = warpM * 64 + (s >> 1) * 16 + (s & 1) * 8 + g;
            Rv[r * 4 + warpN] = best[s];
            Ri[r * 4 + warpN] = bidx[s];
        }
    }
    __syncthreads();
    if (tid < TM) {
        float v = Rv[tid * 4]; int ix = Ri[tid * 4];
        #pragma unroll
        for (int w = 1; w < 4; ++w) {
            float ov = Rv[tid * 4 + w]; int oi = Ri[tid * 4 + w];
            if (ov < v || (ov == v && oi < ix)) { v = ov; ix = oi; }
        }
        g_pidx[js][row0 + tid] = ix;
    }
}

// ---------------- kernel 3: exact fp32 rescue over 8 candidates + row loss ----------------
__global__ void combine_kernel(const float* __restrict__ anc, const float* __restrict__ neg, int B) {
    int row = (blockIdx.x * blockDim.x + threadIdx.x) >> 5;
    int lane = threadIdx.x & 31;
    if (row >= B) return;
    const float4 a = ((const float4*)(anc + (size_t)row * DDIM))[lane];
    float bestd = __int_as_float(0x7f800000);
    int   besti = 0x7fffffff;
    #pragma unroll
    for (int s = 0; s < JSPLIT; ++s) {
        int ix = g_pidx[s][row];
        const float4 n = ((const float4*)(neg + (size_t)ix * DDIM))[lane];
        float d0 = a.x - n.x + EPS, d1 = a.y - n.y + EPS;
        float d2 = a.z - n.z + EPS, d3 = a.w - n.w + EPS;
        float dd = d0*d0 + d1*d1 + d2*d2 + d3*d3;
        #pragma unroll
        for (int off = 16; off; off >>= 1) dd += __shfl_xor_sync(0xffffffffu, dd, off);
        if (dd < bestd || (dd == bestd && ix < besti)) { bestd = dd; besti = ix; }
    }
    if (lane == 0) {
        float t = g_posd[row] - sqrtf(bestd) + MARGIN;
        g_rowloss[row] = t > 0.0f ? t : 0.0f;
    }
}

// ---------------- kernel 4: deterministic mean ----------------
__global__ void final_kernel(float* __restrict__ out, int B) {
    __shared__ float sm[1024];
    float s = 0.0f;
    const float4* rl = (const float4*)g_rowloss;
    for (int i = threadIdx.x; i < B / 4; i += 1024) {
        float4 v = rl[i];
        s += (v.x + v.y) + (v.z + v.w);
    }
    sm[threadIdx.x] = s;
    __syncthreads();
    for (int w = 512; w; w >>= 1) {
        if (threadIdx.x < w) sm[threadIdx.x] += sm[threadIdx.x + w];
        __syncthreads();
    }
    if (threadIdx.x == 0) out[0] = sm[0] / (float)B;
}

// ---------------- launch ----------------
extern "C" void kernel_launch(void* const* d_in, const int* in_sizes, int n_in,
                              void* d_out, int out_size) {
    const float* anc = (const float*)d_in[0];
    const float* pos = (const float*)d_in[1];
    const float* neg = (const float*)d_in[2];
    int B = in_sizes[0] / DDIM;
    float* out = (float*)d_out;

    cudaFuncSetAttribute(gemm_argmin_kernel, cudaFuncAttributeMaxDynamicSharedMemorySize, SMEM_TOTAL);

    prep_kernel<<<(B + 7) / 8, 256>>>(anc, pos, neg, B);
    gemm_argmin_kernel<<<(B / TM) * JSPLIT, 256, SMEM_TOTAL>>>(B);
    combine_kernel<<<(B + 7) / 8, 256>>>(anc, neg, B);
    final_kernel<<<1, 1024>>>(out, B);
}

// round 8
// speedup vs baseline: 1.2676x; 1.0225x over previous
#include <cuda_runtime.h>
#include <cuda_fp16.h>
#include <cstdint>
#include <math.h>

#define EPS    1e-6f
#define MARGIN 0.3f
#define DDIM   128
#define MAXB   16384
#define JSPLIT 8
#define TM     128      // anchor rows per CTA
#define TNT    128      // negatives per tile
#define ROWB   144      // bytes per smem row: 128B data + 16B pad -> conflict-free ldmatrix
#define NBUF_B 18432    // bytes per tile buffer (128*144)

// ---------------- scratch (no allocations allowed) ----------------
__device__ __align__(16) signed char g_Ai8[MAXB * DDIM];
__device__ __align__(16) signed char g_Ni8[MAXB * DDIM];
__device__ __align__(16) float g_ascale[MAXB];
__device__ __align__(16) float g_nscale[MAXB];
__device__ __align__(16) float g_beta[MAXB];    // exact ||n||^2 - 2*eps*sum(n)
__device__ float g_posd[MAXB];
__device__ int   g_pidx[JSPLIT][MAXB];          // slot-winner candidates per row
__device__ float g_rowloss[MAXB];

// ---------------- smem layout (bytes) ----------------
#define OFF_RED    0                 // int[128][4] key reduce
#define OFF_BS     2048              // float[4][128] beta ring
#define OFF_TS     4096              // float[4][128] nscale ring
#define OFF_A      6144              // 128 x ROWB int8 tile (18432 B)
#define OFF_N      24576             // 3 x tile buffer (55296 B)
#define SMEM_TOTAL 79872

__device__ __forceinline__ void mma_s8(int c[4], const uint32_t a[4],
                                       uint32_t b0, uint32_t b1) {
    asm volatile(
        "mma.sync.aligned.m16n8k32.row.col.s32.s8.s8.s32 "
        "{%0,%1,%2,%3}, {%4,%5,%6,%7}, {%8,%9}, {%0,%1,%2,%3};\n"
        : "+r"(c[0]), "+r"(c[1]), "+r"(c[2]), "+r"(c[3])
        : "r"(a[0]), "r"(a[1]), "r"(a[2]), "r"(a[3]), "r"(b0), "r"(b1));
}

__device__ __forceinline__ void ldsm_x4(uint32_t r[4], uint32_t addr) {
    asm volatile("ldmatrix.sync.aligned.m8n8.x4.shared.b16 {%0,%1,%2,%3}, [%4];"
                 : "=r"(r[0]), "=r"(r[1]), "=r"(r[2]), "=r"(r[3]) : "r"(addr));
}

__device__ __forceinline__ void cp_async16(void* dst_smem, const void* src_gmem) {
    unsigned d = (unsigned)__cvta_generic_to_shared(dst_smem);
    asm volatile("cp.async.cg.shared.global [%0], [%1], 16;\n" :: "r"(d), "l"(src_gmem));
}
__device__ __forceinline__ void cp_commit() { asm volatile("cp.async.commit_group;\n"); }

// ---------------- kernel 1: stats + per-row int8 quantization ----------------
__global__ void prep_kernel(const float* __restrict__ anc, const float* __restrict__ pos,
                            const float* __restrict__ neg, int B) {
    int warp = (blockIdx.x * blockDim.x + threadIdx.x) >> 5;
    int lane = threadIdx.x & 31;
    if (warp >= B) return;
    const float4 a = ((const float4*)(anc + (size_t)warp * DDIM))[lane];
    const float4 p = ((const float4*)(pos + (size_t)warp * DDIM))[lane];
    const float4 n = ((const float4*)(neg + (size_t)warp * DDIM))[lane];

    float amax = fmaxf(fmaxf(fabsf(a.x), fabsf(a.y)), fmaxf(fabsf(a.z), fabsf(a.w)));
    float nmax = fmaxf(fmaxf(fabsf(n.x), fabsf(n.y)), fmaxf(fabsf(n.z), fabsf(n.w)));
    float d0 = a.x - p.x + EPS, d1 = a.y - p.y + EPS, d2 = a.z - p.z + EPS, d3 = a.w - p.w + EPS;
    float pd = d0*d0 + d1*d1 + d2*d2 + d3*d3;
    float nn = n.x*n.x + n.y*n.y + n.z*n.z + n.w*n.w;
    float ns = n.x + n.y + n.z + n.w;
    #pragma unroll
    for (int off = 16; off; off >>= 1) {
        amax = fmaxf(amax, __shfl_xor_sync(0xffffffffu, amax, off));
        nmax = fmaxf(nmax, __shfl_xor_sync(0xffffffffu, nmax, off));
        pd += __shfl_xor_sync(0xffffffffu, pd, off);
        nn += __shfl_xor_sync(0xffffffffu, nn, off);
        ns += __shfl_xor_sync(0xffffffffu, ns, off);
    }
    amax = fmaxf(amax, 1e-30f);
    nmax = fmaxf(nmax, 1e-30f);
    float ia = 127.0f / amax, in_ = 127.0f / nmax;

    char4 qa = make_char4((char)__float2int_rn(a.x * ia), (char)__float2int_rn(a.y * ia),
                          (char)__float2int_rn(a.z * ia), (char)__float2int_rn(a.w * ia));
    char4 qn = make_char4((char)__float2int_rn(n.x * in_), (char)__float2int_rn(n.y * in_),
                          (char)__float2int_rn(n.z * in_), (char)__float2int_rn(n.w * in_));
    ((char4*)(g_Ai8 + (size_t)warp * DDIM))[lane] = qa;
    ((char4*)(g_Ni8 + (size_t)warp * DDIM))[lane] = qn;

    if (lane == 0) {
        g_ascale[warp] = amax / 127.0f;
        g_nscale[warp] = nmax / 127.0f;
        g_posd[warp] = sqrtf(pd);
        g_beta[warp] = nn - 2.0f * EPS * ns;
    }
}

// ---------------- tile helpers ----------------
__device__ __forceinline__ void tile_mma(int acc[4][4][4], uint32_t aBase, uint32_t bBase) {
    #pragma unroll
    for (int rt = 0; rt < 4; ++rt)
        #pragma unroll
        for (int nt = 0; nt < 4; ++nt)
            #pragma unroll
            for (int c = 0; c < 4; ++c) acc[rt][nt][c] = 0;
    #pragma unroll
    for (int kk = 0; kk < 4; ++kk) {
        const uint32_t kOff = (uint32_t)kk * 32;
        uint32_t af[4][4], bf[2][4];
        #pragma unroll
        for (int rt = 0; rt < 4; ++rt)
            ldsm_x4(af[rt], aBase + (uint32_t)rt * (16 * ROWB) + kOff);
        #pragma unroll
        for (int np = 0; np < 2; ++np)
            ldsm_x4(bf[np], bBase + (uint32_t)np * (16 * ROWB) + kOff);
        #pragma unroll
        for (int rt = 0; rt < 4; ++rt)
            #pragma unroll
            for (int nt = 0; nt < 4; ++nt)
                mma_s8(acc[rt][nt], af[rt], bf[nt >> 1][(nt & 1) * 2],
                       bf[nt >> 1][(nt & 1) * 2 + 1]);
    }
}

// packed-key epilogue: key = (bits(v) & ~0x7FF) | (t*128 + jc); signed-int min == float min
__device__ __forceinline__ void tile_epi(const int acc[4][4][4], int keys[8],
                                         const float* bsp, const float* tsp,
                                         const float* kA, int colbase, int tloc) {
    #pragma unroll
    for (int nt = 0; nt < 4; ++nt) {
        const int jc = colbase + nt * 8;
        const float b0 = bsp[jc], b1 = bsp[jc + 1];
        const float t0 = tsp[jc], t1 = tsp[jc + 1];
        const int id0 = tloc + jc, id1 = tloc + jc + 1;
        #pragma unroll
        for (int rt = 0; rt < 4; ++rt) {
            const float kl = kA[rt * 2], kh = kA[rt * 2 + 1];
            int k00 = (__float_as_int(fmaf((float)acc[rt][nt][0], kl * t0, b0)) & ~0x7FF) | id0;
            int k01 = (__float_as_int(fmaf((float)acc[rt][nt][1], kl * t1, b1)) & ~0x7FF) | id1;
            int k10 = (__float_as_int(fmaf((float)acc[rt][nt][2], kh * t0, b0)) & ~0x7FF) | id0;
            int k11 = (__float_as_int(fmaf((float)acc[rt][nt][3], kh * t1, b1)) & ~0x7FF) | id1;
            keys[rt * 2]     = min(keys[rt * 2],     min(k00, k01));
            keys[rt * 2 + 1] = min(keys[rt * 2 + 1], min(k10, k11));
        }
    }
}

// ---------------- kernel 2: int8 GEMM + fused argmin, MMA/epilogue pipelined ----------------
__global__ void __launch_bounds__(256, 1) gemm_argmin_kernel(int B) {
    extern __shared__ char smem[];
    float* Bs = (float*)(smem + OFF_BS);
    float* Ts = (float*)(smem + OFF_TS);
    int*   Rk = (int*)(smem + OFF_RED);

    const int tid = threadIdx.x, lane = tid & 31, wid = tid >> 5;
    const int warpM = wid >> 2;                    // 0..1 -> 64 rows
    const int warpN = wid & 3;                     // 0..3 -> 32 cols
    const int g = lane >> 2, q = lane & 3;
    const int colbase = warpN * 32 + 2 * q;

    const int jlen   = B / JSPLIT;                 // 2048 (11-bit local index)
    const int rowT   = blockIdx.x / JSPLIT;
    const int js     = blockIdx.x % JSPLIT;
    const int row0   = rowT * TM;
    const int jbase0 = js * jlen;
    const int ntiles = jlen / TNT;                 // 16

    unsigned sb = (unsigned)__cvta_generic_to_shared(smem);

    float kA[8];
    #pragma unroll
    for (int rt = 0; rt < 4; ++rt) {
        int r = row0 + warpM * 64 + rt * 16 + g;
        kA[rt * 2]     = -2.0f * g_ascale[r];
        kA[rt * 2 + 1] = -2.0f * g_ascale[r + 8];
    }

    const uint32_t aBase = sb + OFF_A
        + (uint32_t)(warpM * 64 + (lane & 15)) * ROWB + (uint32_t)(lane >> 4) * 16;
    const uint32_t bRel = (uint32_t)(warpN * 32 + (lane & 7) + ((lane >> 4) & 1) * 8) * ROWB
        + (uint32_t)((lane >> 3) & 1) * 16;

    auto load_A = [&]() {
        for (int i = tid; i < TM * 8; i += 256) {
            int r = i >> 3, f = i & 7;
            cp_async16(smem + OFF_A + r * ROWB + f * 16,
                       g_Ai8 + (size_t)(row0 + r) * DDIM + f * 16);
        }
    };
    auto load_N = [&](int tile) {
        if (tile < ntiles) {
            const int jb = jbase0 + tile * TNT;
            char* dst = smem + OFF_N + (tile % 3) * NBUF_B;
            for (int i = tid; i < TNT * 8; i += 256) {
                int r = i >> 3, f = i & 7;
                cp_async16(dst + r * ROWB + f * 16, g_Ni8 + (size_t)(jb + r) * DDIM + f * 16);
            }
            if (tid < 32)
                cp_async16(Bs + (tile & 3) * 128 + tid * 4, g_beta + jb + tid * 4);
            else if (tid < 64)
                cp_async16(Ts + (tile & 3) * 128 + (tid - 32) * 4, g_nscale + jb + (tid - 32) * 4);
        }
    };
    auto bBaseOf = [&](int tile) {
        return sb + OFF_N + (uint32_t)(tile % 3) * NBUF_B + bRel;
    };

    // prologue
    load_A(); load_N(0); cp_commit();              // g0 = {A, N0, rings0}
    load_N(1); cp_commit();                        // g1 = {N1, rings1}
    asm volatile("cp.async.wait_group 1;\n");      // g0 done
    __syncthreads();

    int keys[8];
    #pragma unroll
    for (int s = 0; s < 8; ++s) keys[s] = 0x7F800000;

    int acc0[4][4][4], acc1[4][4][4];
    tile_mma(acc0, aBase, bBaseOf(0));             // MMA tile 0 in flight

    for (int t = 0; t < ntiles; t += 2) {
        // --- tile t in acc0; issue t+1 into acc1, then epilogue t ---
        load_N(t + 2); cp_commit();
        if (t + 1 < ntiles) {
            asm volatile("cp.async.wait_group 1;\n");
            __syncthreads();
            tile_mma(acc1, aBase, bBaseOf(t + 1));
        }
        tile_epi(acc0, keys, Bs + (t & 3) * 128, Ts + (t & 3) * 128, kA, colbase, t << 7);
        __syncthreads();

        // --- tile t+1 in acc1; issue t+2 into acc0, then epilogue t+1 ---
        if (t + 1 < ntiles) {
            load_N(t + 3); cp_commit();
            if (t + 2 < ntiles) {
                asm volatile("cp.async.wait_group 1;\n");
                __syncthreads();
                tile_mma(acc0, aBase, bBaseOf(t + 2));
            }
            tile_epi(acc1, keys, Bs + ((t + 1) & 3) * 128, Ts + ((t + 1) & 3) * 128,
                     kA, colbase, (t + 1) << 7);
            __syncthreads();
        }
    }

    // quad reduce (lanes sharing a row differ only in q) on packed keys
    #pragma unroll
    for (int s = 0; s < 8; ++s) {
        int k = keys[s];
        #pragma unroll
        for (int off = 1; off <= 2; off <<= 1)
            k = min(k, __shfl_xor_sync(0xffffffffu, k, off));
        keys[s] = k;
    }
    if (q == 0) {
        #pragma unroll
        for (int s = 0; s < 8; ++s) {
            int r = warpM * 64 + (s >> 1) * 16 + (s & 1) * 8 + g;
            Rk[r * 4 + warpN] = keys[s];
        }
    }
    __syncthreads();
    if (tid < TM) {
        int k = Rk[tid * 4];
        #pragma unroll
        for (int w = 1; w < 4; ++w) k = min(k, Rk[tid * 4 + w]);
        g_pidx[js][row0 + tid] = jbase0 + (k & 0x7FF);
    }
}

// ---------------- kernel 3: exact fp32 rescue over 8 candidates + row loss ----------------
__global__ void combine_kernel(const float* __restrict__ anc, const float* __restrict__ neg, int B) {
    int row = (blockIdx.x * blockDim.x + threadIdx.x) >> 5;
    int lane = threadIdx.x & 31;
    if (row >= B) return;
    const float4 a = ((const float4*)(anc + (size_t)row * DDIM))[lane];
    float bestd = __int_as_float(0x7f800000);
    int   besti = 0x7fffffff;
    #pragma unroll
    for (int s = 0; s < JSPLIT; ++s) {
        int ix = g_pidx[s][row];
        const float4 n = ((const float4*)(neg + (size_t)ix * DDIM))[lane];
        float d0 = a.x - n.x + EPS, d1 = a.y - n.y + EPS;
        float d2 = a.z - n.z + EPS, d3 = a.w - n.w + EPS;
        float dd = d0*d0 + d1*d1 + d2*d2 + d3*d3;
        #pragma unroll
        for (int off = 16; off; off >>= 1) dd += __shfl_xor_sync(0xffffffffu, dd, off);
        if (dd < bestd || (dd == bestd && ix < besti)) { bestd = dd; besti = ix; }
    }
    if (lane == 0) {
        float t = g_posd[row] - sqrtf(bestd) + MARGIN;
        g_rowloss[row] = t > 0.0f ? t : 0.0f;
    }
}

// ---------------- kernel 4: deterministic mean ----------------
__global__ void final_kernel(float* __restrict__ out, int B) {
    __shared__ float sm[1024];
    float s = 0.0f;
    const float4* rl = (const float4*)g_rowloss;
    for (int i = threadIdx.x; i < B / 4; i += 1024) {
        float4 v = rl[i];
        s += (v.x + v.y) + (v.z + v.w);
    }
    sm[threadIdx.x] = s;
    __syncthreads();
    for (int w = 512; w; w >>= 1) {
        if (threadIdx.x < w) sm[threadIdx.x] += sm[threadIdx.x + w];
        __syncthreads();
    }
    if (threadIdx.x == 0) out[0] = sm[0] / (float)B;
}

// ---------------- launch ----------------
extern "C" void kernel_launch(void* const* d_in, const int* in_sizes, int n_in,
                              void* d_out, int out_size) {
    const float* anc = (const float*)d_in[0];
    const float* pos = (const float*)d_in[1];
    const float* neg = (const float*)d_in[2];
    int B = in_sizes[0] / DDIM;
    float* out = (float*)d_out;

    cudaFuncSetAttribute(gemm_argmin_kernel, cudaFuncAttributeMaxDynamicSharedMemorySize, SMEM_TOTAL);

    prep_kernel<<<(B + 7) / 8, 256>>>(anc, pos, neg, B);
    gemm_argmin_kernel<<<(B / TM) * JSPLIT, 256, SMEM_TOTAL>>>(B);
    combine_kernel<<<(B + 7) / 8, 256>>>(anc, neg, B);
    final_kernel<<<1, 1024>>>(out, B);
}

// round 10
// speedup vs baseline: 1.5859x; 1.2511x over previous
#include <cuda_runtime.h>
#include <cuda_fp16.h>
#include <cstdint>
#include <math.h>

#define EPS    1e-6f
#define MARGIN 0.3f
#define DDIM   128
#define MAXB   16384
#define JSPLIT 8
#define TM     128      // anchor rows per CTA
#define TNT    128      // negatives per tile
#define ROWB   144      // bytes per smem row: 128B data + 16B pad -> conflict-free ldmatrix
#define NBUF_B 18432    // bytes per tile buffer (128*144)

// ---------------- scratch (no allocations allowed) ----------------
__device__ __align__(16) signed char g_Ai8[MAXB * DDIM];
__device__ __align__(16) signed char g_Ni8[MAXB * DDIM];
__device__ __align__(16) float g_ascale[MAXB];
__device__ __align__(16) float g_nscale[MAXB];
__device__ __align__(16) float g_beta[MAXB];    // exact ||n||^2 - 2*eps*sum(n)
__device__ float g_posd[MAXB];
__device__ int   g_pidx[JSPLIT][MAXB];          // slot-winner candidates per row
__device__ float g_rowloss[MAXB];

// ---------------- smem layout (bytes) ----------------
#define OFF_RED    0                 // int[128][4] key reduce
#define OFF_BS     2048              // float[4][128] beta ring
#define OFF_TS     4096              // float[4][128] nscale ring
#define OFF_A      6144              // 128 x ROWB int8 tile (18432 B)
#define OFF_N      24576             // 3 x tile buffer (55296 B)
#define SMEM_TOTAL 79872             // x2 CTAs = 156 KB/SM

__device__ __forceinline__ void mma_s8(int c[4], const uint32_t a[4],
                                       uint32_t b0, uint32_t b1) {
    asm volatile(
        "mma.sync.aligned.m16n8k32.row.col.s32.s8.s8.s32 "
        "{%0,%1,%2,%3}, {%4,%5,%6,%7}, {%8,%9}, {%0,%1,%2,%3};\n"
        : "+r"(c[0]), "+r"(c[1]), "+r"(c[2]), "+r"(c[3])
        : "r"(a[0]), "r"(a[1]), "r"(a[2]), "r"(a[3]), "r"(b0), "r"(b1));
}

__device__ __forceinline__ void ldsm_x4(uint32_t r[4], uint32_t addr) {
    asm volatile("ldmatrix.sync.aligned.m8n8.x4.shared.b16 {%0,%1,%2,%3}, [%4];"
                 : "=r"(r[0]), "=r"(r[1]), "=r"(r[2]), "=r"(r[3]) : "r"(addr));
}

__device__ __forceinline__ void cp_async16(void* dst_smem, const void* src_gmem) {
    unsigned d = (unsigned)__cvta_generic_to_shared(dst_smem);
    asm volatile("cp.async.cg.shared.global [%0], [%1], 16;\n" :: "r"(d), "l"(src_gmem));
}
__device__ __forceinline__ void cp_commit() { asm volatile("cp.async.commit_group;\n"); }

// ---------------- kernel 1: stats + per-row int8 quantization ----------------
__global__ void prep_kernel(const float* __restrict__ anc, const float* __restrict__ pos,
                            const float* __restrict__ neg, int B) {
    int warp = (blockIdx.x * blockDim.x + threadIdx.x) >> 5;
    int lane = threadIdx.x & 31;
    if (warp >= B) return;
    const float4 a = ((const float4*)(anc + (size_t)warp * DDIM))[lane];
    const float4 p = ((const float4*)(pos + (size_t)warp * DDIM))[lane];
    const float4 n = ((const float4*)(neg + (size_t)warp * DDIM))[lane];

    float amax = fmaxf(fmaxf(fabsf(a.x), fabsf(a.y)), fmaxf(fabsf(a.z), fabsf(a.w)));
    float nmax = fmaxf(fmaxf(fabsf(n.x), fabsf(n.y)), fmaxf(fabsf(n.z), fabsf(n.w)));
    float d0 = a.x - p.x + EPS, d1 = a.y - p.y + EPS, d2 = a.z - p.z + EPS, d3 = a.w - p.w + EPS;
    float pd = d0*d0 + d1*d1 + d2*d2 + d3*d3;
    float nn = n.x*n.x + n.y*n.y + n.z*n.z + n.w*n.w;
    float ns = n.x + n.y + n.z + n.w;
    #pragma unroll
    for (int off = 16; off; off >>= 1) {
        amax = fmaxf(amax, __shfl_xor_sync(0xffffffffu, amax, off));
        nmax = fmaxf(nmax, __shfl_xor_sync(0xffffffffu, nmax, off));
        pd += __shfl_xor_sync(0xffffffffu, pd, off);
        nn += __shfl_xor_sync(0xffffffffu, nn, off);
        ns += __shfl_xor_sync(0xffffffffu, ns, off);
    }
    amax = fmaxf(amax, 1e-30f);
    nmax = fmaxf(nmax, 1e-30f);
    float ia = 127.0f / amax, in_ = 127.0f / nmax;

    char4 qa = make_char4((char)__float2int_rn(a.x * ia), (char)__float2int_rn(a.y * ia),
                          (char)__float2int_rn(a.z * ia), (char)__float2int_rn(a.w * ia));
    char4 qn = make_char4((char)__float2int_rn(n.x * in_), (char)__float2int_rn(n.y * in_),
                          (char)__float2int_rn(n.z * in_), (char)__float2int_rn(n.w * in_));
    ((char4*)(g_Ai8 + (size_t)warp * DDIM))[lane] = qa;
    ((char4*)(g_Ni8 + (size_t)warp * DDIM))[lane] = qn;

    if (lane == 0) {
        g_ascale[warp] = amax / 127.0f;
        g_nscale[warp] = nmax / 127.0f;
        g_posd[warp] = sqrtf(pd);
        g_beta[warp] = nn - 2.0f * EPS * ns;
    }
}

// ---------------- kernel 2: int8 GEMM + fused argmin, 2 CTAs/SM ----------------
// 256 threads. Warp grid 2(M) x 4(N); warp tile 64x32. K=128 in 4 k32 steps.
__global__ void __launch_bounds__(256, 2) gemm_argmin_kernel(int B) {
    extern __shared__ char smem[];
    float* Bs = (float*)(smem + OFF_BS);
    float* Ts = (float*)(smem + OFF_TS);
    int*   Rk = (int*)(smem + OFF_RED);

    const int tid = threadIdx.x, lane = tid & 31, wid = tid >> 5;
    const int warpM = wid >> 2;                    // 0..1 -> 64 rows
    const int warpN = wid & 3;                     // 0..3 -> 32 cols
    const int g = lane >> 2, q = lane & 3;
    const int colbase = warpN * 32 + 2 * q;

    const int jlen   = B / JSPLIT;                 // 2048 (11-bit local index)
    const int rowT   = blockIdx.x / JSPLIT;
    const int js     = blockIdx.x % JSPLIT;
    const int row0   = rowT * TM;
    const int jbase0 = js * jlen;
    const int ntiles = jlen / TNT;                 // 16

    unsigned sb = (unsigned)__cvta_generic_to_shared(smem);

    float kA[8];
    #pragma unroll
    for (int rt = 0; rt < 4; ++rt) {
        int r = row0 + warpM * 64 + rt * 16 + g;
        kA[rt * 2]     = -2.0f * g_ascale[r];
        kA[rt * 2 + 1] = -2.0f * g_ascale[r + 8];
    }

    const uint32_t aBase = sb + OFF_A
        + (uint32_t)(warpM * 64 + (lane & 15)) * ROWB + (uint32_t)(lane >> 4) * 16;
    const uint32_t bRel = (uint32_t)(warpN * 32 + (lane & 7) + ((lane >> 4) & 1) * 8) * ROWB
        + (uint32_t)((lane >> 3) & 1) * 16;

    auto load_A = [&]() {
        for (int i = tid; i < TM * 8; i += 256) {
            int r = i >> 3, f = i & 7;
            cp_async16(smem + OFF_A + r * ROWB + f * 16,
                       g_Ai8 + (size_t)(row0 + r) * DDIM + f * 16);
        }
    };
    auto load_N = [&](int tile) {
        if (tile < ntiles) {
            const int jb = jbase0 + tile * TNT;
            char* dst = smem + OFF_N + (tile % 3) * NBUF_B;
            for (int i = tid; i < TNT * 8; i += 256) {
                int r = i >> 3, f = i & 7;
                cp_async16(dst + r * ROWB + f * 16, g_Ni8 + (size_t)(jb + r) * DDIM + f * 16);
            }
            if (tid < 32)
                cp_async16(Bs + (tile & 3) * 128 + tid * 4, g_beta + jb + tid * 4);
            else if (tid < 64)
                cp_async16(Ts + (tile & 3) * 128 + (tid - 32) * 4, g_nscale + jb + (tid - 32) * 4);
        }
    };

    load_A(); load_N(0); cp_commit();
    load_N(1); cp_commit();

    int keys[8];
    #pragma unroll
    for (int s = 0; s < 8; ++s) keys[s] = 0x7F800000;

    for (int t = 0; t < ntiles; ++t) {
        asm volatile("cp.async.wait_group 1;\n");
        __syncthreads();

        int acc[4][4][4];
        #pragma unroll
        for (int rt = 0; rt < 4; ++rt)
            #pragma unroll
            for (int nt = 0; nt < 4; ++nt)
                #pragma unroll
                for (int c = 0; c < 4; ++c) acc[rt][nt][c] = 0;

        const uint32_t bBase = sb + OFF_N + (uint32_t)(t % 3) * NBUF_B + bRel;
        #pragma unroll
        for (int kk = 0; kk < 4; ++kk) {
            const uint32_t kOff = (uint32_t)kk * 32;
            uint32_t af[4][4], bf[2][4];
            #pragma unroll
            for (int rt = 0; rt < 4; ++rt)
                ldsm_x4(af[rt], aBase + (uint32_t)rt * (16 * ROWB) + kOff);
            #pragma unroll
            for (int np = 0; np < 2; ++np)
                ldsm_x4(bf[np], bBase + (uint32_t)np * (16 * ROWB) + kOff);
            #pragma unroll
            for (int rt = 0; rt < 4; ++rt)
                #pragma unroll
                for (int nt = 0; nt < 4; ++nt)
                    mma_s8(acc[rt][nt], af[rt], bf[nt >> 1][(nt & 1) * 2],
                           bf[nt >> 1][(nt & 1) * 2 + 1]);
        }

        load_N(t + 2);
        cp_commit();

        // packed-key epilogue: key = (bits(v) & ~0x7FF) | (t*128 + jc)
        const float* bsp = Bs + (t & 3) * 128;
        const float* tsp = Ts + (t & 3) * 128;
        const int tloc = t << 7;
        #pragma unroll
        for (int nt = 0; nt < 4; ++nt) {
            const int jc = colbase + nt * 8;
            const float b0 = bsp[jc], b1 = bsp[jc + 1];
            const float t0 = tsp[jc], t1 = tsp[jc + 1];
            const int id0 = tloc + jc, id1 = tloc + jc + 1;
            #pragma unroll
            for (int rt = 0; rt < 4; ++rt) {
                const float kl = kA[rt * 2], kh = kA[rt * 2 + 1];
                int k00 = (__float_as_int(fmaf((float)acc[rt][nt][0], kl * t0, b0)) & ~0x7FF) | id0;
                int k01 = (__float_as_int(fmaf((float)acc[rt][nt][1], kl * t1, b1)) & ~0x7FF) | id1;
                int k10 = (__float_as_int(fmaf((float)acc[rt][nt][2], kh * t0, b0)) & ~0x7FF) | id0;
                int k11 = (__float_as_int(fmaf((float)acc[rt][nt][3], kh * t1, b1)) & ~0x7FF) | id1;
                keys[rt * 2]     = min(keys[rt * 2],     min(k00, k01));
                keys[rt * 2 + 1] = min(keys[rt * 2 + 1], min(k10, k11));
            }
        }
    }

    // quad reduce (lanes sharing a row differ only in q) on packed keys
    #pragma unroll
    for (int s = 0; s < 8; ++s) {
        int k = keys[s];
        #pragma unroll
        for (int off = 1; off <= 2; off <<= 1)
            k = min(k, __shfl_xor_sync(0xffffffffu, k, off));
        keys[s] = k;
    }
    if (q == 0) {
        #pragma unroll
        for (int s = 0; s < 8; ++s) {
            int r = warpM * 64 + (s >> 1) * 16 + (s & 1) * 8 + g;
            Rk[r * 4 + warpN] = keys[s];
        }
    }
    __syncthreads();
    if (tid < TM) {
        int k = Rk[tid * 4];
        #pragma unroll
        for (int w = 1; w < 4; ++w) k = min(k, Rk[tid * 4 + w]);
        g_pidx[js][row0 + tid] = jbase0 + (k & 0x7FF);
    }
}

// ---------------- kernel 3: exact fp32 rescue over 8 candidates + row loss ----------------
__global__ void combine_kernel(const float* __restrict__ anc, const float* __restrict__ neg, int B) {
    int row = (blockIdx.x * blockDim.x + threadIdx.x) >> 5;
    int lane = threadIdx.x & 31;
    if (row >= B) return;
    const float4 a = ((const float4*)(anc + (size_t)row * DDIM))[lane];
    float bestd = __int_as_float(0x7f800000);
    int   besti = 0x7fffffff;
    #pragma unroll
    for (int s = 0; s < JSPLIT; ++s) {
        int ix = g_pidx[s][row];
        const float4 n = ((const float4*)(neg + (size_t)ix * DDIM))[lane];
        float d0 = a.x - n.x + EPS, d1 = a.y - n.y + EPS;
        float d2 = a.z - n.z + EPS, d3 = a.w - n.w + EPS;
        float dd = d0*d0 + d1*d1 + d2*d2 + d3*d3;
        #pragma unroll
        for (int off = 16; off; off >>= 1) dd += __shfl_xor_sync(0xffffffffu, dd, off);
        if (dd < bestd || (dd == bestd && ix < besti)) { bestd = dd; besti = ix; }
    }
    if (lane == 0) {
        float t = g_posd[row] - sqrtf(bestd) + MARGIN;
        g_rowloss[row] = t > 0.0f ? t : 0.0f;
    }
}

// ---------------- kernel 4: deterministic mean ----------------
__global__ void final_kernel(float* __restrict__ out, int B) {
    __shared__ float sm[1024];
    float s = 0.0f;
    const float4* rl = (const float4*)g_rowloss;
    for (int i = threadIdx.x; i < B / 4; i += 1024) {
        float4 v = rl[i];
        s += (v.x + v.y) + (v.z + v.w);
    }
    sm[threadIdx.x] = s;
    __syncthreads();
    for (int w = 512; w; w >>= 1) {
        if (threadIdx.x < w) sm[threadIdx.x] += sm[threadIdx.x + w];
        __syncthreads();
    }
    if (threadIdx.x == 0) out[0] = sm[0] / (float)B;
}

// ---------------- launch ----------------
extern "C" void kernel_launch(void* const* d_in, const int* in_sizes, int n_in,
                              void* d_out, int out_size) {
    const float* anc = (const float*)d_in[0];
    const float* pos = (const float*)d_in[1];
    const float* neg = (const float*)d_in[2];
    int B = in_sizes[0] / DDIM;
    float* out = (float*)d_out;

    cudaFuncSetAttribute(gemm_argmin_kernel, cudaFuncAttributeMaxDynamicSharedMemorySize, SMEM_TOTAL);

    prep_kernel<<<(B + 7) / 8, 256>>>(anc, pos, neg, B);
    gemm_argmin_kernel<<<(B / TM) * JSPLIT, 256, SMEM_TOTAL>>>(B);
    combine_kernel<<<(B + 7) / 8, 256>>>(anc, neg, B);
    final_kernel<<<1, 1024>>>(out, B);
}